// round 3
// baseline (speedup 1.0000x reference)
#include <cuda_runtime.h>

// BigBird block-sparse attention, fp32 flash-style, sm_103a.
// Shapes (hardcoded from setup_inputs): B=2, H=12, S=4096, D=64, BLOCK=64, nb=64, r=3.

#define NEGV (-10000.0f)

constexpr int Bb = 2;
constexpr int Hh = 12;
constexpr int Ss = 4096;
constexpr int Dd = 64;
constexpr int BS = 64;      // block size
constexpr int NB = Ss / BS; // 64 blocks
constexpr int Rr = 3;

constexpr int SQ = 65;  // Q smem stride (padded: read along d)
constexpr int SK = 65;  // K smem stride (padded: read along d)
constexpr int SV = 64;  // V smem stride (bank varies with col -> no pad)
constexpr int SP = 64;  // P smem stride (broadcast reads -> no pad)

constexpr int SMEM_FLOATS = BS * SQ + BS * SK + BS * SV + BS * SP + 64;
constexpr int SMEM_BYTES  = SMEM_FLOATS * 4;  // 66304 B

__global__ void __launch_bounds__(256, 3) bigbird_kernel(
    const float* __restrict__ q,
    const float* __restrict__ k,
    const float* __restrict__ v,
    const float* __restrict__ mask,      // [B, S]
    const int*   __restrict__ rand_attn, // [B, H, NB-2, R]
    float* __restrict__ out)
{
    extern __shared__ float sm[];
    float* Qs = sm;               // 64*65
    float* Ks = Qs + BS * SQ;     // 64*65
    float* Vs = Ks + BS * SK;     // 64*64
    float* Ps = Vs + BS * SV;     // 64*64
    float* Ms = Ps + BS * SP;     // 64 key-mask values

    // ---- decode CTA -> (b, h, qb); heavy full-attention blocks first ----
    const int BH = Bb * Hh;
    int bid = blockIdx.x;
    int qb, idx;
    if (bid < BH)            { qb = 0;        idx = bid; }
    else if (bid < 2 * BH)   { qb = NB - 1;   idx = bid - BH; }
    else { int m = bid - 2 * BH; qb = 1 + m / BH; idx = m % BH; }
    const int b = idx / Hh, h = idx % Hh;

    const int tid = threadIdx.x;
    const int ti = tid >> 4;      // 0..15 : row group (rows 4*ti .. 4*ti+3)
    const int tj = tid & 15;      // 0..15 : col lane  (cols tj, tj+16, tj+32, tj+48)

    const float scale = 0.125f;   // 1/sqrt(64)

    // ---- load Q block into smem ----
    const size_t bh = (size_t)(b * Hh + h);
    const float* qptr = q + (bh * Ss + (size_t)qb * BS) * Dd;
    for (int e = tid; e < BS * Dd; e += 256) {
        int r = e >> 6, c = e & 63;
        Qs[r * SQ + c] = qptr[e];
    }

    // ---- build key-block list ----
    int kblocks[8];
    int ntile;
    const bool full = (qb == 0) || (qb == NB - 1);
    if (full) {
        ntile = NB;
    } else {
        const int* rp = rand_attn + (((size_t)(b * Hh + h)) * (NB - 2) + (qb - 1)) * Rr;
        const int r0 = rp[0], r1 = rp[1], r2 = rp[2];
        if (qb == 1) {
            kblocks[0] = 0; kblocks[1] = 1; kblocks[2] = 2; kblocks[3] = NB - 1;
            kblocks[4] = r0; kblocks[5] = r1; kblocks[6] = r2; ntile = 7;
        } else if (qb == NB - 2) {
            kblocks[0] = 0; kblocks[1] = NB - 3; kblocks[2] = NB - 2; kblocks[3] = NB - 1;
            kblocks[4] = r0; kblocks[5] = r1; kblocks[6] = r2; ntile = 7;
        } else {
            kblocks[0] = 0; kblocks[1] = qb - 1; kblocks[2] = qb; kblocks[3] = qb + 1;
            kblocks[4] = r0; kblocks[5] = r1; kblocks[6] = r2; kblocks[7] = NB - 1; ntile = 8;
        }
    }

    float acc[4][4];
    #pragma unroll
    for (int a = 0; a < 4; a++)
        #pragma unroll
        for (int c = 0; c < 4; c++) acc[a][c] = 0.0f;
    float mrow[4], lrow[4];
    #pragma unroll
    for (int a = 0; a < 4; a++) { mrow[a] = -1e30f; lrow[a] = 0.0f; }

    const float* kbase = k + bh * Ss * Dd;
    const float* vbase = v + bh * Ss * Dd;
    const float* mbase = mask + (size_t)b * Ss;

    for (int t = 0; t < ntile; t++) {
        const int kb = full ? t : kblocks[t];

        __syncthreads();  // prev tile's V/K consumers done
        const float* kp = kbase + (size_t)kb * BS * Dd;
        const float* vp = vbase + (size_t)kb * BS * Dd;
        for (int e = tid; e < BS * Dd; e += 256) {
            int r = e >> 6, c = e & 63;
            Ks[r * SK + c] = kp[e];
            Vs[r * SV + c] = vp[e];
        }
        if (tid < 64) Ms[tid] = mbase[kb * BS + tid];
        __syncthreads();

        // ---- scores: s[a][c] = Q[4ti+a] . K[tj+16c] ----
        float s[4][4];
        #pragma unroll
        for (int a = 0; a < 4; a++)
            #pragma unroll
            for (int c = 0; c < 4; c++) s[a][c] = 0.0f;

        #pragma unroll 8
        for (int d = 0; d < Dd; d++) {
            float qv[4], kv[4];
            #pragma unroll
            for (int a = 0; a < 4; a++) qv[a] = Qs[(4 * ti + a) * SQ + d];
            #pragma unroll
            for (int c = 0; c < 4; c++) kv[c] = Ks[(tj + 16 * c) * SK + d];
            #pragma unroll
            for (int a = 0; a < 4; a++)
                #pragma unroll
                for (int c = 0; c < 4; c++) s[a][c] += qv[a] * kv[c];
        }

        float km[4];
        #pragma unroll
        for (int c = 0; c < 4; c++) km[c] = (1.0f - Ms[tj + 16 * c]) * NEGV;
        #pragma unroll
        for (int a = 0; a < 4; a++)
            #pragma unroll
            for (int c = 0; c < 4; c++) s[a][c] = s[a][c] * scale + km[c];

        // ---- online softmax update ----
        #pragma unroll
        for (int a = 0; a < 4; a++) {
            float mm = fmaxf(fmaxf(s[a][0], s[a][1]), fmaxf(s[a][2], s[a][3]));
            mm = fmaxf(mm, __shfl_xor_sync(0xffffffffu, mm, 1));
            mm = fmaxf(mm, __shfl_xor_sync(0xffffffffu, mm, 2));
            mm = fmaxf(mm, __shfl_xor_sync(0xffffffffu, mm, 4));
            mm = fmaxf(mm, __shfl_xor_sync(0xffffffffu, mm, 8));
            const float mnew = fmaxf(mrow[a], mm);
            const float corr = __expf(mrow[a] - mnew);
            float ls = 0.0f;
            #pragma unroll
            for (int c = 0; c < 4; c++) {
                float p = __expf(s[a][c] - mnew);
                Ps[(4 * ti + a) * SP + tj + 16 * c] = p;
                ls += p;
            }
            ls += __shfl_xor_sync(0xffffffffu, ls, 1);
            ls += __shfl_xor_sync(0xffffffffu, ls, 2);
            ls += __shfl_xor_sync(0xffffffffu, ls, 4);
            ls += __shfl_xor_sync(0xffffffffu, ls, 8);
            lrow[a] = lrow[a] * corr + ls;
            mrow[a] = mnew;
            #pragma unroll
            for (int c = 0; c < 4; c++) acc[a][c] *= corr;
        }
        __syncwarp();  // P row written by 16 lanes of this ti group (same warp)

        // ---- PV accumulate ----
        #pragma unroll 4
        for (int j = 0; j < BS; j++) {
            float pv[4], vv[4];
            #pragma unroll
            for (int a = 0; a < 4; a++) pv[a] = Ps[(4 * ti + a) * SP + j];
            #pragma unroll
            for (int c = 0; c < 4; c++) vv[c] = Vs[j * SV + tj + 16 * c];
            #pragma unroll
            for (int a = 0; a < 4; a++)
                #pragma unroll
                for (int c = 0; c < 4; c++) acc[a][c] += pv[a] * vv[c];
        }
    }

    // ---- epilogue: normalize, apply from_mask, write ----
    float* optr = out + (bh * Ss + (size_t)qb * BS) * Dd;
    #pragma unroll
    for (int a = 0; a < 4; a++) {
        const int row = 4 * ti + a;
        const float fm = mbase[qb * BS + row];
        const float inv = fm / lrow[a];
        #pragma unroll
        for (int c = 0; c < 4; c++)
            optr[row * Dd + tj + 16 * c] = acc[a][c] * inv;
    }
}

extern "C" void kernel_launch(void* const* d_in, const int* in_sizes, int n_in,
                              void* d_out, int out_size)
{
    const float* q    = (const float*)d_in[0];
    const float* k    = (const float*)d_in[1];
    const float* v    = (const float*)d_in[2];
    const float* mask = (const float*)d_in[3];
    const int*   ra   = (const int*)d_in[4];
    float* out = (float*)d_out;

    cudaFuncSetAttribute(bigbird_kernel,
                         cudaFuncAttributeMaxDynamicSharedMemorySize, SMEM_BYTES);

    const int grid = Bb * Hh * NB;  // 1536 CTAs, heavy blocks first
    bigbird_kernel<<<grid, 256, SMEM_BYTES>>>(q, k, v, mask, ra, out);
}